// round 16
// baseline (speedup 1.0000x reference)
#include <cuda_runtime.h>
#include <cuda_bf16.h>

// Problem constants (from reference)
#define N_WORDS   100000
#define N_DIMS    128
#define N_SAMPLES 65536
#define K_NEG     10

constexpr int LANES_PER_SAMPLE  = 16;                     // 4 shuffle stages
constexpr int SAMPLES_PER_WARP  = 32 / LANES_PER_SAMPLE;  // 2
constexpr int WARPS_PER_BLOCK   = 8;
constexpr int THREADS           = WARPS_PER_BLOCK * 32;   // 256
constexpr int SAMPLES_PER_BLOCK = WARPS_PER_BLOCK * SAMPLES_PER_WARP;  // 16
constexpr int NBLOCKS = N_SAMPLES / SAMPLES_PER_BLOCK;    // 4096

// Static device scratch (no runtime allocation allowed).
// bf16 copy of W_out: 100000 * 128 * 2B = 25.6 MB -> fits easily in L2.
__device__ __nv_bfloat16 g_Wout_bf16[(size_t)N_WORDS * N_DIMS];
__device__ float g_partials[NBLOCKS];
__device__ unsigned int g_done_count;   // zero at load; last block resets each launch

// Numerically stable log-sigmoid: logsig(x) = min(x,0) - log1p(exp(-|x|))
__device__ __forceinline__ float log_sigmoid(float x) {
    return fminf(x, 0.0f) - log1pf(__expf(-fabsf(x)));
}

__device__ __forceinline__ float dot4(const float4 a, const float4 c) {
    return a.x * c.x + a.y * c.y + a.z * c.z + a.w * c.w;
}

// Exact bf16->fp32: low half = element 2j, high half = element 2j+1
__device__ __forceinline__ float bf_lo(unsigned int w) { return __uint_as_float(w << 16); }
__device__ __forceinline__ float bf_hi(unsigned int w) { return __uint_as_float(w & 0xffff0000u); }

// ---------------------------------------------------------------------------
// Kernel 1: convert W_out fp32 -> bf16 (streamed; runs every launch, so it is
// deterministic and replay-safe). Each thread: 8 floats -> 1 uint4 of bf16.
// ---------------------------------------------------------------------------
constexpr int CONV_THREADS = 256;
constexpr long long CONV_TOTAL = (long long)N_WORDS * N_DIMS / 8;   // 1.6M
constexpr int CONV_BLOCKS = (int)((CONV_TOTAL + CONV_THREADS - 1) / CONV_THREADS);

__global__ void __launch_bounds__(CONV_THREADS)
convert_wout_kernel(const float* __restrict__ W_out)
{
    long long t = (long long)blockIdx.x * CONV_THREADS + threadIdx.x;
    if (t >= CONV_TOTAL) return;
    const float4* src = reinterpret_cast<const float4*>(W_out) + t * 2;
    float4 f0 = __ldcs(src);          // streaming: don't pollute L2 with fp32
    float4 f1 = __ldcs(src + 1);
    __nv_bfloat162 p0 = __floats2bfloat162_rn(f0.x, f0.y);
    __nv_bfloat162 p1 = __floats2bfloat162_rn(f0.z, f0.w);
    __nv_bfloat162 p2 = __floats2bfloat162_rn(f1.x, f1.y);
    __nv_bfloat162 p3 = __floats2bfloat162_rn(f1.z, f1.w);
    uint4 out;
    out.x = *reinterpret_cast<unsigned int*>(&p0);
    out.y = *reinterpret_cast<unsigned int*>(&p1);
    out.z = *reinterpret_cast<unsigned int*>(&p2);
    out.w = *reinterpret_cast<unsigned int*>(&p3);
    reinterpret_cast<uint4*>(g_Wout_bf16)[t] = out;
}

// ---------------------------------------------------------------------------
// Kernel 2: fused skipgram loss. 16 lanes per sample; lane `sub` owns dims
// [8*sub, 8*sub+8). bf16 row slice = one uint4 per lane (256B/row coalesced).
// ---------------------------------------------------------------------------
__global__ void __launch_bounds__(THREADS, 4)
skipgram_fused_kernel(const int* __restrict__ input_idx,
                      const int* __restrict__ output_idx,
                      const int* __restrict__ neg_idx,
                      const float* __restrict__ W_in,
                      float* __restrict__ out)
{
    const int warp  = threadIdx.x >> 5;
    const int lane  = threadIdx.x & 31;
    const int group = lane >> 4;          // 0..1  (sample within warp)
    const int sub   = lane & 15;          // 0..15 (slice within sample)
    const int s = blockIdx.x * SAMPLES_PER_BLOCK + warp * SAMPLES_PER_WARP + group;

    const float4* __restrict__ Win4 = reinterpret_cast<const float4*>(W_in);
    const uint4*  __restrict__ Wo   = reinterpret_cast<const uint4*>(g_Wout_bf16);

    const int ii = __ldg(input_idx  + s);
    const int oi = __ldg(output_idx + s);

    int nidx[K_NEG];
    #pragma unroll
    for (int k = 0; k < K_NEG; k++)
        nidx[k] = __ldg(neg_idx + (size_t)s * K_NEG + k);

    // fp32 in-vec: lane's 8 dims = two consecutive float4 (2*sub, 2*sub+1)
    const float4* arow = Win4 + (size_t)ii * 32;
    const float4 a0 = __ldg(arow + 2 * sub);
    const float4 a1 = __ldg(arow + 2 * sub + 1);

    float vals[K_NEG + 1];

    // Positive dot: bf16 out-vec row, one uint4 (8 bf16) per lane
    {
        const uint4 w = __ldg(Wo + (size_t)oi * 16 + sub);
        float4 c0 = make_float4(bf_lo(w.x), bf_hi(w.x), bf_lo(w.y), bf_hi(w.y));
        float4 c1 = make_float4(bf_lo(w.z), bf_hi(w.z), bf_lo(w.w), bf_hi(w.w));
        vals[0] = dot4(a0, c0) + dot4(a1, c1);
    }

    // Negative dots
    #pragma unroll
    for (int k = 0; k < K_NEG; k++) {
        const uint4 w = __ldg(Wo + (size_t)nidx[k] * 16 + sub);
        float4 c0 = make_float4(bf_lo(w.x), bf_hi(w.x), bf_lo(w.y), bf_hi(w.y));
        float4 c1 = make_float4(bf_lo(w.z), bf_hi(w.z), bf_lo(w.w), bf_hi(w.w));
        vals[k + 1] = dot4(a0, c0) + dot4(a1, c1);
    }

    // Reduce across the 16 lanes of each sample group (xor<16 stays in-group)
    #pragma unroll
    for (int j = 0; j < K_NEG + 1; j++) {
        #pragma unroll
        for (int off = 8; off > 0; off >>= 1)
            vals[j] += __shfl_xor_sync(0xffffffffu, vals[j], off);
    }

    __shared__ float sample_loss[SAMPLES_PER_BLOCK];
    if (sub == 0) {
        float loss = log_sigmoid(vals[0]);
        #pragma unroll
        for (int k = 0; k < K_NEG; k++)
            loss += log_sigmoid(-vals[k + 1]);
        sample_loss[warp * SAMPLES_PER_WARP + group] = loss;
    }
    __syncthreads();

    // Deterministic in-block reduction (fixed order, thread 0) + arrival mark
    __shared__ bool is_last;
    if (threadIdx.x == 0) {
        float bsum = 0.0f;
        #pragma unroll
        for (int i = 0; i < SAMPLES_PER_BLOCK; i++) bsum += sample_loss[i];
        g_partials[blockIdx.x] = bsum;
        __threadfence();                      // publish partial before counting
        unsigned int t = atomicAdd(&g_done_count, 1u);
        is_last = (t == NBLOCKS - 1);
    }
    __syncthreads();

    // Last block: fixed-order final reduction in double (deterministic)
    if (is_last) {
        __shared__ double sh[THREADS];
        const int tid = threadIdx.x;
        double acc = 0.0;
        for (int i = tid; i < NBLOCKS; i += THREADS)   // fixed strided order
            acc += (double)g_partials[i];
        sh[tid] = acc;
        __syncthreads();
        for (int off = THREADS / 2; off > 0; off >>= 1) {
            if (tid < off) sh[tid] += sh[tid + off];
            __syncthreads();
        }
        if (tid == 0) {
            out[0] = (float)(sh[0] / (double)N_SAMPLES);
            g_done_count = 0;                 // reset for next graph replay
        }
    }
}

extern "C" void kernel_launch(void* const* d_in, const int* in_sizes, int n_in,
                              void* d_out, int out_size)
{
    const int*   input_idx  = (const int*)  d_in[0];
    const int*   output_idx = (const int*)  d_in[1];
    const int*   neg_idx    = (const int*)  d_in[2];
    const float* W_in       = (const float*)d_in[3];
    const float* W_out      = (const float*)d_in[4];
    float*       out        = (float*)d_out;

    convert_wout_kernel<<<CONV_BLOCKS, CONV_THREADS>>>(W_out);
    skipgram_fused_kernel<<<NBLOCKS, THREADS>>>(input_idx, output_idx, neg_idx,
                                                W_in, out);
}

// round 17
// speedup vs baseline: 1.0450x; 1.0450x over previous
#include <cuda_runtime.h>
#include <cuda_fp16.h>

// Problem constants (from reference)
#define N_WORDS   100000
#define N_DIMS    128
#define N_SAMPLES 65536
#define K_NEG     10

constexpr int LANES_PER_SAMPLE  = 16;                     // 4 shuffle stages
constexpr int SAMPLES_PER_WARP  = 32 / LANES_PER_SAMPLE;  // 2
constexpr int WARPS_PER_BLOCK   = 8;
constexpr int THREADS           = WARPS_PER_BLOCK * 32;   // 256
constexpr int SAMPLES_PER_BLOCK = WARPS_PER_BLOCK * SAMPLES_PER_WARP;  // 16
constexpr int NBLOCKS = N_SAMPLES / SAMPLES_PER_BLOCK;    // 4096

// Static device scratch (no runtime allocation allowed).
// fp16 copy of W_out: 100000 * 128 * 2B = 25.6 MB -> L2-resident.
__device__ __half g_Wout_h[(size_t)N_WORDS * N_DIMS];
__device__ float g_partials[NBLOCKS];
__device__ unsigned int g_done_count;   // zero at load; last block resets each launch

// Numerically stable log-sigmoid: logsig(x) = min(x,0) - log1p(exp(-|x|))
__device__ __forceinline__ float log_sigmoid(float x) {
    return fminf(x, 0.0f) - log1pf(__expf(-fabsf(x)));
}

// ---------------------------------------------------------------------------
// Kernel 1: convert W_out fp32 -> fp16 (runs every launch; deterministic).
// Each thread: 8 floats -> 1 uint4 of halves.
// ---------------------------------------------------------------------------
constexpr int CONV_THREADS = 256;
constexpr long long CONV_TOTAL = (long long)N_WORDS * N_DIMS / 8;   // 1.6M
constexpr int CONV_BLOCKS = (int)((CONV_TOTAL + CONV_THREADS - 1) / CONV_THREADS);

__global__ void __launch_bounds__(CONV_THREADS)
convert_wout_kernel(const float* __restrict__ W_out)
{
    long long t = (long long)blockIdx.x * CONV_THREADS + threadIdx.x;
    if (t >= CONV_TOTAL) return;
    const float4* src = reinterpret_cast<const float4*>(W_out) + t * 2;
    float4 f0 = __ldcs(src);          // streaming read: don't pollute L2 with fp32
    float4 f1 = __ldcs(src + 1);
    __half2 p0 = __floats2half2_rn(f0.x, f0.y);
    __half2 p1 = __floats2half2_rn(f0.z, f0.w);
    __half2 p2 = __floats2half2_rn(f1.x, f1.y);
    __half2 p3 = __floats2half2_rn(f1.z, f1.w);
    uint4 out;
    out.x = *reinterpret_cast<unsigned int*>(&p0);
    out.y = *reinterpret_cast<unsigned int*>(&p1);
    out.z = *reinterpret_cast<unsigned int*>(&p2);
    out.w = *reinterpret_cast<unsigned int*>(&p3);
    reinterpret_cast<uint4*>(g_Wout_h)[t] = out;   // normal store: keep in L2
}

// ---------------------------------------------------------------------------
// Kernel 2: fused skipgram loss. 16 lanes/sample; lane `sub` owns dims
// [8*sub, 8*sub+8). fp16 row slice = one uint4 (8 halves), fed straight into
// 4 HFMA2 — no unpack ALU at all.
// ---------------------------------------------------------------------------
__global__ void __launch_bounds__(THREADS, 4)
skipgram_fused_kernel(const int* __restrict__ input_idx,
                      const int* __restrict__ output_idx,
                      const int* __restrict__ neg_idx,
                      const float* __restrict__ W_in,
                      float* __restrict__ out)
{
    const int warp  = threadIdx.x >> 5;
    const int lane  = threadIdx.x & 31;
    const int group = lane >> 4;          // 0..1  (sample within warp)
    const int sub   = lane & 15;          // 0..15 (slice within sample)
    const int s = blockIdx.x * SAMPLES_PER_BLOCK + warp * SAMPLES_PER_WARP + group;

    const float4* __restrict__ Win4 = reinterpret_cast<const float4*>(W_in);
    const uint4*  __restrict__ Wo   = reinterpret_cast<const uint4*>(g_Wout_h);

    const int ii = __ldg(input_idx  + s);
    const int oi = __ldg(output_idx + s);

    // neg_idx row is 10 contiguous ints at byte offset 40*s (8B-aligned) -> 5x int2
    int nidx[K_NEG];
    {
        const int2* np = reinterpret_cast<const int2*>(neg_idx + (size_t)s * K_NEG);
        #pragma unroll
        for (int k = 0; k < 5; k++) {
            int2 p = __ldg(np + k);
            nidx[2 * k]     = p.x;
            nidx[2 * k + 1] = p.y;
        }
    }

    // fp32 in-vec slice (8 dims), converted once to 4 half2
    const float4* arow = Win4 + (size_t)ii * 32;
    const float4 a0 = __ldg(arow + 2 * sub);
    const float4 a1 = __ldg(arow + 2 * sub + 1);
    __half2 ah[4];
    ah[0] = __floats2half2_rn(a0.x, a0.y);
    ah[1] = __floats2half2_rn(a0.z, a0.w);
    ah[2] = __floats2half2_rn(a1.x, a1.y);
    ah[3] = __floats2half2_rn(a1.z, a1.w);

    float vals[K_NEG + 1];

    // One dot partial per lane: 4 chained HFMA2 on the gathered uint4
    auto dot_row = [&](const uint4 w) -> float {
        const __half2* wh = reinterpret_cast<const __half2*>(&w);
        __half2 acc = __hmul2(ah[0], wh[0]);
        acc = __hfma2(ah[1], wh[1], acc);
        acc = __hfma2(ah[2], wh[2], acc);
        acc = __hfma2(ah[3], wh[3], acc);
        return __low2float(acc) + __high2float(acc);
    };

    vals[0] = dot_row(__ldg(Wo + (size_t)oi * 16 + sub));
    #pragma unroll
    for (int k = 0; k < K_NEG; k++)
        vals[k + 1] = dot_row(__ldg(Wo + (size_t)nidx[k] * 16 + sub));

    // Reduce across the 16 lanes of each sample group (xor<16 stays in-group)
    #pragma unroll
    for (int j = 0; j < K_NEG + 1; j++) {
        #pragma unroll
        for (int off = 8; off > 0; off >>= 1)
            vals[j] += __shfl_xor_sync(0xffffffffu, vals[j], off);
    }

    __shared__ float sample_loss[SAMPLES_PER_BLOCK];
    if (sub == 0) {
        float loss = log_sigmoid(vals[0]);
        #pragma unroll
        for (int k = 0; k < K_NEG; k++)
            loss += log_sigmoid(-vals[k + 1]);
        sample_loss[warp * SAMPLES_PER_WARP + group] = loss;
    }
    __syncthreads();

    // Deterministic in-block reduction (fixed order, thread 0) + arrival mark
    __shared__ bool is_last;
    if (threadIdx.x == 0) {
        float bsum = 0.0f;
        #pragma unroll
        for (int i = 0; i < SAMPLES_PER_BLOCK; i++) bsum += sample_loss[i];
        g_partials[blockIdx.x] = bsum;
        __threadfence();                      // publish partial before counting
        unsigned int t = atomicAdd(&g_done_count, 1u);
        is_last = (t == NBLOCKS - 1);
    }
    __syncthreads();

    // Last block: fixed-order final reduction in double (deterministic)
    if (is_last) {
        __shared__ double sh[THREADS];
        const int tid = threadIdx.x;
        double acc = 0.0;
        for (int i = tid; i < NBLOCKS; i += THREADS)   // fixed strided order
            acc += (double)g_partials[i];
        sh[tid] = acc;
        __syncthreads();
        for (int off = THREADS / 2; off > 0; off >>= 1) {
            if (tid < off) sh[tid] += sh[tid + off];
            __syncthreads();
        }
        if (tid == 0) {
            out[0] = (float)(sh[0] / (double)N_SAMPLES);
            g_done_count = 0;                 // reset for next graph replay
        }
    }
}

extern "C" void kernel_launch(void* const* d_in, const int* in_sizes, int n_in,
                              void* d_out, int out_size)
{
    const int*   input_idx  = (const int*)  d_in[0];
    const int*   output_idx = (const int*)  d_in[1];
    const int*   neg_idx    = (const int*)  d_in[2];
    const float* W_in       = (const float*)d_in[3];
    const float* W_out      = (const float*)d_in[4];
    float*       out        = (float*)d_out;

    convert_wout_kernel<<<CONV_BLOCKS, CONV_THREADS>>>(W_out);
    skipgram_fused_kernel<<<NBLOCKS, THREADS>>>(input_idx, output_idx, neg_idx,
                                                W_in, out);
}